// round 12
// baseline (speedup 1.0000x reference)
#include <cuda_runtime.h>
#include <cuda_fp16.h>
#include <math.h>

#define NN 50000
#define NP 50048
#define EE 400000
#define RR 4
#define MM (RR*NN)
#define SCAN_BLOCKS ((MM + 4095) / 4096)   // 49

#define FMA2(acc, w, a) asm("fma.rn.f32x2 %0, %1, %2, %0;" : "+l"(acc) : "l"(w), "l"(a))
#define PACK2(dst, lo, hi) asm("mov.b64 %0, {%1, %2};" : "=l"(dst) : "f"(lo), "f"(hi))
#define UNPACK2(lo, hi, src) asm("mov.b64 {%0, %1}, %2;" : "=f"(lo), "=f"(hi) : "l"(src))
#define CP_ASYNC16(saddr, gptr) \
    asm volatile("cp.async.cg.shared.global [%0], [%1], 16;" :: "r"(saddr), "l"(gptr))
#define CP_COMMIT() asm volatile("cp.async.commit_group;")
#define CP_WAIT0() asm volatile("cp.async.wait_group 0;" ::: "memory")

__device__ __forceinline__ unsigned smem_u32(const void* p) {
    return (unsigned)__cvta_generic_to_shared(p);
}

// ---------------- device scratch ----------------
__device__ __align__(16) float g_h2[NP * 64];
__device__ __align__(16) __half2 g_Hr[(size_t)RR * NP * 64];
__device__ __align__(16) float g_es[RR * NP * 2];
__device__ __align__(16) float g_ed[RR * NP * 2];
__device__ __align__(16) __half g_Fh[(size_t)NN * 512];   // fp16 GAT outputs (gather->mlp)
__device__ __align__(16) float g_wa[16 * 64];
__device__ int g_deg[MM];           // zero at entry: zero-init first call, re-zeroed by k_scan3
__device__ int g_indptr[MM + 1];
__device__ int g_cursor[MM];
__device__ int g_nbr[2 * EE];
__device__ int g_blksum[64];
__device__ int g_blkoff[64];

// ---------------- CSR build ----------------
__global__ void k_hist(const int* __restrict__ ei, const float* __restrict__ ew) {
    int e = blockIdx.x * 256 + threadIdx.x;
    if (e >= EE) return;
    int s = ei[e];
    int d = ei[EE + e];
    float w = ew[e];
    if (w > 0.f) {
        atomicAdd(&g_deg[0 * NN + d], 1);
        atomicAdd(&g_deg[1 * NN + s], 1);
    } else if (w < 0.f) {
        atomicAdd(&g_deg[2 * NN + d], 1);
        atomicAdd(&g_deg[3 * NN + s], 1);
    }
}

__global__ void k_scan1() {
    __shared__ int sd[512];
    int t = threadIdx.x;
    int base = blockIdx.x * 4096 + t * 8;
    int v[8];
    int s = 0;
#pragma unroll
    for (int i = 0; i < 8; i++) {
        int idx = base + i;
        int x = (idx < MM) ? g_deg[idx] : 0;
        v[i] = s;
        s += x;
    }
    sd[t] = s;
    __syncthreads();
    int tot = s;
    for (int off = 1; off < 512; off <<= 1) {
        int y = (t >= off) ? sd[t - off] : 0;
        __syncthreads();
        sd[t] += y;
        __syncthreads();
    }
    int excl = sd[t] - tot;
#pragma unroll
    for (int i = 0; i < 8; i++) {
        int idx = base + i;
        if (idx < MM) g_indptr[idx] = excl + v[i];
    }
    if (t == 511) g_blksum[blockIdx.x] = sd[511];
}

__global__ void k_scan2(int nblk) {
    int lane = threadIdx.x;
    int v0 = (lane < nblk) ? g_blksum[lane] : 0;
    int v1 = (32 + lane < nblk) ? g_blksum[32 + lane] : 0;
    int s0 = v0;
#pragma unroll
    for (int off = 1; off < 32; off <<= 1) {
        int t = __shfl_up_sync(0xffffffffu, s0, off);
        if (lane >= off) s0 += t;
    }
    int tot0 = __shfl_sync(0xffffffffu, s0, 31);
    int s1 = v1;
#pragma unroll
    for (int off = 1; off < 32; off <<= 1) {
        int t = __shfl_up_sync(0xffffffffu, s1, off);
        if (lane >= off) s1 += t;
    }
    s1 += tot0;
    if (lane < nblk) g_blkoff[lane] = s0 - v0;
    if (32 + lane < nblk) g_blkoff[32 + lane] = s1 - v1;
    if (lane == 31) g_indptr[MM] = s1;
}

__global__ void k_scan3() {
    int off = g_blkoff[blockIdx.x];
    int idx = blockIdx.x * 4096 + threadIdx.x;
#pragma unroll
    for (int i = 0; i < 8; i++, idx += 512) {
        if (idx < MM) {
            int val = g_indptr[idx] + off;
            g_indptr[idx] = val;
            g_cursor[idx] = val;
            g_deg[idx] = 0;          // restore invariant for next call
        }
    }
}

__global__ void k_scatter(const int* __restrict__ ei, const float* __restrict__ ew) {
    int e = blockIdx.x * 256 + threadIdx.x;
    if (e >= EE) return;
    int s = ei[e];
    int d = ei[EE + e];
    float w = ew[e];
    if (w > 0.f) {
        int p0 = atomicAdd(&g_cursor[0 * NN + d], 1); g_nbr[p0] = s;
        int p1 = atomicAdd(&g_cursor[1 * NN + s], 1); g_nbr[p1] = d;
    } else if (w < 0.f) {
        int p2 = atomicAdd(&g_cursor[2 * NN + d], 1); g_nbr[p2] = s;
        int p3 = atomicAdd(&g_cursor[3 * NN + s], 1); g_nbr[p3] = d;
    }
}

// ---------------- wa = W @ a ----------------
__global__ void k_wa(const float* __restrict__ W,
                     const float* __restrict__ asrc,
                     const float* __restrict__ adst, int l) {
    __shared__ float as_[64];
    int o = blockIdx.x;
    int r = o >> 2, sdm = (o >> 1) & 1, hd = o & 1;
    const float* a = (sdm ? adst : asrc) + ((size_t)(l * RR + r) * 2 + hd) * 64;
    int tid = threadIdx.x;
    if (tid < 64) as_[tid] = a[tid];
    __syncthreads();
    int w = tid >> 5, lane = tid & 31;
    float a0 = as_[lane], a1 = as_[lane + 32];
    for (int kk = 0; kk < 32; kk++) {
        int k = w * 32 + kk;
        const float* Wrow = W + ((size_t)(l * RR + r) * 64 + k) * 128 + hd * 64;
        float s = Wrow[lane] * a0 + Wrow[lane + 32] * a1;
#pragma unroll
        for (int o2 = 16; o2; o2 >>= 1) s += __shfl_down_sync(0xffffffffu, s, o2);
        if (lane == 0) g_wa[o * 64 + k] = s;
    }
}

// ---------------- attention logits ----------------
__global__ void k_logits(const float* __restrict__ xin, int l, int useX) {
    __shared__ float hs[16 * 65];
    __shared__ float was[16 * 65];
    const float* hin = useX ? xin : g_h2;
    int tid = threadIdx.x;
    int n0 = blockIdx.x * 16;
    for (int t = tid; t < 16 * 64; t += 256) {
        int nn = t >> 6, k = t & 63;
        hs[nn * 65 + k] = hin[(size_t)(n0 + nn) * 64 + k];
        was[nn * 65 + k] = g_wa[t];
    }
    __syncthreads();
    int o = tid & 15;
    int nn = tid >> 4;
    const float* hrow = hs + nn * 65;
    const float* wrow = was + o * 65;
    float s = 0.f;
#pragma unroll 8
    for (int k = 0; k < 64; k++) s += hrow[k] * wrow[k];
    int r = o >> 2, sdm = (o >> 1) & 1, hd = o & 1;
    float* dst = (sdm ? g_ed : g_es) + ((size_t)r * NP + n0 + nn) * 2 + hd;
    *dst = s;
}

// ---------------- per-relation feature GEMM: 4 cols x 16 nodes / thread, fp16 out ----------------
__global__ __launch_bounds__(128) void k_feat(const float* __restrict__ xin,
                                              const float* __restrict__ W,
                                              int l, int useX) {
    __shared__ __align__(16) float Ws[64 * 128];
    __shared__ __align__(16) float hsT[64 * 68];

    const float* hin = useX ? xin : g_h2;
    const int t = threadIdx.x;
    const int r = blockIdx.y;
    const int jc = t & 31;
    const int half = t >> 5;
    const float* Wp = W + (size_t)(l * RR + r) * 64 * 128;
#pragma unroll 8
    for (int k = 0; k < 64; k++) Ws[k * 128 + t] = Wp[k * 128 + t];
    int n0 = blockIdx.x * 64;
    for (int q = t; q < 64 * 64; q += 128) {
        int nn = q >> 6, k = q & 63;
        int n = n0 + nn;
        hsT[k * 68 + nn] = (n < NN) ? hin[(size_t)n * 64 + k] : 0.f;
    }
    __syncthreads();

    unsigned long long acc[4][8];
#pragma unroll
    for (int c = 0; c < 4; c++)
#pragma unroll
        for (int p = 0; p < 8; p++) acc[c][p] = 0ull;

#pragma unroll 2
    for (int k = 0; k < 64; k++) {
        float w0 = Ws[k * 128 + jc];
        float w1 = Ws[k * 128 + jc + 32];
        float w2 = Ws[k * 128 + jc + 64];
        float w3 = Ws[k * 128 + jc + 96];
        unsigned long long wp0, wp1, wp2, wp3;
        PACK2(wp0, w0, w0); PACK2(wp1, w1, w1);
        PACK2(wp2, w2, w2); PACK2(wp3, w3, w3);
        const ulonglong2* hp = (const ulonglong2*)&hsT[k * 68 + half * 16];
#pragma unroll
        for (int q = 0; q < 4; q++) {
            ulonglong2 a = hp[q];
            FMA2(acc[0][2 * q], wp0, a.x); FMA2(acc[0][2 * q + 1], wp0, a.y);
            FMA2(acc[1][2 * q], wp1, a.x); FMA2(acc[1][2 * q + 1], wp1, a.y);
            FMA2(acc[2][2 * q], wp2, a.x); FMA2(acc[2][2 * q + 1], wp2, a.y);
            FMA2(acc[3][2 * q], wp3, a.x); FMA2(acc[3][2 * q + 1], wp3, a.y);
        }
    }
    __half2* Hrow = g_Hr + (size_t)r * NP * 64;
    int nb = n0 + half * 16;
#pragma unroll
    for (int p = 0; p < 8; p++) {
        float l0, h0, l1, h1, l2, h2, l3, h3;
        UNPACK2(l0, h0, acc[0][p]);
        UNPACK2(l1, h1, acc[1][p]);
        UNPACK2(l2, h2, acc[2][p]);
        UNPACK2(l3, h3, acc[3][p]);
        Hrow[(size_t)(nb + 2 * p) * 64 + jc]          = __floats2half2_rn(l0, l1);
        Hrow[(size_t)(nb + 2 * p + 1) * 64 + jc]      = __floats2half2_rn(h0, h1);
        Hrow[(size_t)(nb + 2 * p) * 64 + 32 + jc]     = __floats2half2_rn(l2, l3);
        Hrow[(size_t)(nb + 2 * p + 1) * 64 + 32 + jc] = __floats2half2_rn(h2, h3);
    }
}

// ---------------- CSR gather: batched index prefetch (8-wide), fp16 F out ----------------
__global__ void k_gather(const float* __restrict__ gbias, int l) {
    int gw = (blockIdx.x * 256 + threadIdx.x) >> 5;
    int lane = threadIdx.x & 31;
    if (gw >= MM) return;
    int r = gw / NN;
    int d = gw - r * NN;
    int hd = lane >> 4;
    int cbase = hd * 64 + 2 * (lane & 15);

    const float* esr = g_es + (size_t)r * NP * 2;
    float edv = g_ed[((size_t)r * NP + d) * 2 + hd];
    const uint2* Hp = (const uint2*)(g_Hr + (size_t)r * NP * 64);

    // self loop
    float e0 = esr[d * 2 + hd] + edv;
    e0 = fmaxf(e0, 0.2f * e0);
    float p = __expf(e0);
    uint2 sv = Hp[(size_t)d * 32 + lane];
    float2 f0 = __half22float2(*(__half2*)&sv.x);
    float2 f1 = __half22float2(*(__half2*)&sv.y);
    float a0 = p * f0.x, a1 = p * f1.x, a2 = p * f0.y, a3 = p * f1.y;
    float den = p;

    int beg = g_indptr[gw];
    int end = g_indptr[gw + 1];
    for (int base = beg; base < end; base += 8) {
        int m = end - base;            // >=1
        int idx[8];
#pragma unroll
        for (int q = 0; q < 8; q++)
            idx[q] = (q < m) ? g_nbr[base + q] : d;    // safe pad; contribution zeroed below
        float pv[8];
        uint2 uv[8];
#pragma unroll
        for (int q = 0; q < 8; q++) {
            float e = esr[idx[q] * 2 + hd] + edv;
            e = fmaxf(e, 0.2f * e);
            pv[q] = __expf(e);
            uv[q] = Hp[(size_t)idx[q] * 32 + lane];
        }
#pragma unroll
        for (int q = 0; q < 8; q++) {
            float pq = (q < m) ? pv[q] : 0.f;
            float2 g0 = __half22float2(*(__half2*)&uv[q].x);
            float2 g1 = __half22float2(*(__half2*)&uv[q].y);
            den += pq;
            a0 += pq * g0.x; a1 += pq * g1.x; a2 += pq * g0.y; a3 += pq * g1.y;
        }
    }

    float inv = 1.f / den;
    const float* bp = gbias + (size_t)(l * RR + r) * 128 + cbase;
    __half2* Fd = (__half2*)(g_Fh + (size_t)d * 512 + r * 128 + cbase);
    Fd[0]  = __floats2half2_rn(a0 * inv + bp[0], a1 * inv + bp[1]);
    Fd[16] = __floats2half2_rn(a2 * inv + bp[32], a3 * inv + bp[33]);
}

// ---------------- MLP + residual + LayerNorm: cp.async double-buffered, fp16 F in ----------------
__global__ __launch_bounds__(128) void k_mlp(const float* __restrict__ xin,
                      const float* __restrict__ W1,
                      const float* __restrict__ b1,
                      const float* __restrict__ W2,
                      const float* __restrict__ b2,
                      const float* __restrict__ lng,
                      const float* __restrict__ lnb,
                      int l, float* __restrict__ outbuf, int isLast, int useX) {
    extern __shared__ __align__(16) float sm[];
    float* scomb = sm;                        // 16*576 = 9216 floats
    float* wbuf0 = scomb + 16 * 576;          // 4096
    float* wbuf1 = wbuf0 + 4096;              // 4096
    float* sRed = wbuf1 + 4096;               // 64

    const float* hin = useX ? xin : g_h2;
    float* hout = isLast ? outbuf : g_h2;

    int tid = threadIdx.x;
    int j = tid & 63;
    int g = tid >> 6;
    int lane = tid & 31;
    int w2 = (tid >> 5) & 1;
    int n0 = blockIdx.x * 16;

    const float* W1p = W1 + (size_t)l * 576 * 64;
    const float* W2p = W2 + (size_t)l * 4096;

    unsigned s_scomb = smem_u32(scomb);
    unsigned s_w0 = smem_u32(wbuf0);

#pragma unroll
    for (int i = 0; i < 2; i++) {
        int c4 = tid + i * 128;
        int nn = c4 >> 4, k4 = c4 & 15;
        CP_ASYNC16(s_scomb + (nn * 576 + k4 * 4) * 4,
                   hin + (size_t)(n0 + nn) * 64 + k4 * 4);
    }
#pragma unroll
    for (int i = 0; i < 8; i++) {
        int c4 = tid + i * 128;
        CP_ASYNC16(s_w0 + c4 * 16, W1p + c4 * 4);
    }
    CP_COMMIT();

#pragma unroll
    for (int i = 0; i < 16; i++) {
        int c = tid + i * 128;
        int nn = c >> 7, k4 = c & 127;
        uint2 raw = *(const uint2*)(g_Fh + (size_t)(n0 + nn) * 512 + k4 * 4);
        float2 f0 = __half22float2(*(__half2*)&raw.x);
        float2 f1 = __half22float2(*(__half2*)&raw.y);
        *(float4*)(scomb + nn * 576 + 64 + k4 * 4) = make_float4(f0.x, f0.y, f1.x, f1.y);
    }
    CP_WAIT0();
    __syncthreads();

    unsigned long long accA[8], accB[8];
#pragma unroll
    for (int n = 0; n < 8; n++) { accA[n] = 0ull; accB[n] = 0ull; }

    for (int kt = 0; kt < 9; kt++) {
        const float* nxt = (kt < 8) ? (W1p + (kt + 1) * 4096) : W2p;
        unsigned dstb = (kt & 1) ? s_w0 : smem_u32(wbuf1);
#pragma unroll
        for (int i = 0; i < 8; i++) {
            int c4 = tid + i * 128;
            CP_ASYNC16(dstb + c4 * 16, nxt + c4 * 4);
        }
        CP_COMMIT();

        const float* Wt = (kt & 1) ? wbuf1 : wbuf0;
#pragma unroll 4
        for (int kk4 = 0; kk4 < 16; kk4++) {
            float w0 = Wt[(kk4 * 4 + 0) * 64 + j];
            float w1 = Wt[(kk4 * 4 + 1) * 64 + j];
            float w2f = Wt[(kk4 * 4 + 2) * 64 + j];
            float w3 = Wt[(kk4 * 4 + 3) * 64 + j];
            unsigned long long wp01, wp23;
            PACK2(wp01, w0, w1);
            PACK2(wp23, w2f, w3);
#pragma unroll
            for (int n = 0; n < 8; n++) {
                ulonglong2 a = ((const ulonglong2*)(scomb + (g * 8 + n) * 576))[kt * 16 + kk4];
                FMA2(accA[n], wp01, a.x);
                FMA2(accB[n], wp23, a.y);
            }
        }
        CP_WAIT0();
        __syncthreads();
    }

    float bb = b1[l * 64 + j];
#pragma unroll
    for (int n = 0; n < 8; n++) {
        float lo, hi, lo2, hi2;
        UNPACK2(lo, hi, accA[n]);
        UNPACK2(lo2, hi2, accB[n]);
        scomb[(g * 8 + n) * 576 + 64 + j] = tanhf(bb + lo + hi + lo2 + hi2);
    }
    __syncthreads();

    const float* Wt2 = wbuf1;
    unsigned long long zA[8], zB[8];
#pragma unroll
    for (int n = 0; n < 8; n++) { zA[n] = 0ull; zB[n] = 0ull; }
#pragma unroll 4
    for (int kk4 = 0; kk4 < 16; kk4++) {
        float w0 = Wt2[(kk4 * 4 + 0) * 64 + j];
        float w1 = Wt2[(kk4 * 4 + 1) * 64 + j];
        float w2f = Wt2[(kk4 * 4 + 2) * 64 + j];
        float w3 = Wt2[(kk4 * 4 + 3) * 64 + j];
        unsigned long long wp01, wp23;
        PACK2(wp01, w0, w1);
        PACK2(wp23, w2f, w3);
#pragma unroll
        for (int n = 0; n < 8; n++) {
            ulonglong2 a = ((const ulonglong2*)(scomb + (g * 8 + n) * 576 + 64))[kk4];
            FMA2(zA[n], wp01, a.x);
            FMA2(zB[n], wp23, a.y);
        }
    }
    float z[8];
    float bb2 = b2[l * 64 + j];
#pragma unroll
    for (int n = 0; n < 8; n++) {
        float lo, hi, lo2, hi2;
        UNPACK2(lo, hi, zA[n]);
        UNPACK2(lo2, hi2, zB[n]);
        z[n] = bb2 + lo + hi + lo2 + hi2 + scomb[(g * 8 + n) * 576 + j];
    }

#pragma unroll
    for (int n = 0; n < 8; n++) {
        float a = z[n], bsq = z[n] * z[n];
#pragma unroll
        for (int o = 16; o; o >>= 1) {
            a += __shfl_down_sync(0xffffffffu, a, o);
            bsq += __shfl_down_sync(0xffffffffu, bsq, o);
        }
        if (lane == 0) {
            sRed[((g * 2 + w2) * 8 + n) * 2 + 0] = a;
            sRed[((g * 2 + w2) * 8 + n) * 2 + 1] = bsq;
        }
    }
    __syncthreads();

    float gj = lng[l * 64 + j];
    float bj = lnb[l * 64 + j];
#pragma unroll
    for (int n = 0; n < 8; n++) {
        float su = sRed[((g * 2 + 0) * 8 + n) * 2 + 0] + sRed[((g * 2 + 1) * 8 + n) * 2 + 0];
        float sq = sRed[((g * 2 + 0) * 8 + n) * 2 + 1] + sRed[((g * 2 + 1) * 8 + n) * 2 + 1];
        float mu = su * (1.f / 64.f);
        float var = sq * (1.f / 64.f) - mu * mu;
        float nrm = rsqrtf(var + 1e-5f);
        int n_ = n0 + g * 8 + n;
        hout[(size_t)n_ * 64 + j] = (z[n] - mu) * nrm * gj + bj;
    }
}

// ---------------- launch ----------------
extern "C" void kernel_launch(void* const* d_in, const int* in_sizes, int n_in,
                              void* d_out, int out_size) {
    const float* x   = (const float*)d_in[0];
    const int*   ei  = (const int*)d_in[1];
    const float* ew  = (const float*)d_in[2];
    const float* gW  = (const float*)d_in[3];
    const float* gas = (const float*)d_in[4];
    const float* gad = (const float*)d_in[5];
    const float* gb  = (const float*)d_in[6];
    const float* W1  = (const float*)d_in[7];
    const float* b1  = (const float*)d_in[8];
    const float* W2  = (const float*)d_in[9];
    const float* b2  = (const float*)d_in[10];
    const float* lg  = (const float*)d_in[11];
    const float* lb  = (const float*)d_in[12];
    float* out = (float*)d_out;

    const int mlp_smem = (16 * 576 + 4096 + 4096 + 64) * 4;   // 69888 B
    cudaFuncSetAttribute(k_mlp, cudaFuncAttributeMaxDynamicSharedMemorySize, mlp_smem);

    k_wa<<<16, 64>>>(gW, gas, gad, 0);
    k_logits<<<NN / 16, 256>>>(x, 0, 1);
    k_feat<<<dim3((NP + 63) / 64, RR), 128>>>(x, gW, 0, 1);
    k_hist<<<(EE + 255) / 256, 256>>>(ei, ew);
    k_scan1<<<SCAN_BLOCKS, 512>>>();
    k_scan2<<<1, 32>>>(SCAN_BLOCKS);
    k_scan3<<<SCAN_BLOCKS, 512>>>();
    k_scatter<<<(EE + 255) / 256, 256>>>(ei, ew);

    k_gather<<<MM / 8, 256>>>(gb, 0);
    k_mlp<<<NN / 16, 128, mlp_smem>>>(x, W1, b1, W2, b2, lg, lb, 0, out, 0, 1);

    // layer 1
    k_wa<<<16, 64>>>(gW, gas, gad, 1);
    k_logits<<<NN / 16, 256>>>(x, 1, 0);
    k_feat<<<dim3((NP + 63) / 64, RR), 128>>>(x, gW, 1, 0);
    k_gather<<<MM / 8, 256>>>(gb, 1);
    k_mlp<<<NN / 16, 128, mlp_smem>>>(x, W1, b1, W2, b2, lg, lb, 1, out, 1, 0);
}

// round 14
// speedup vs baseline: 1.0557x; 1.0557x over previous
#include <cuda_runtime.h>
#include <cuda_fp16.h>
#include <math.h>

#define NN 50000
#define NP 50048
#define EE 400000
#define RR 4
#define MM (RR*NN)
#define SCAN_BLOCKS ((MM + 4095) / 4096)   // 49

#define FMA2(acc, w, a) asm("fma.rn.f32x2 %0, %1, %2, %0;" : "+l"(acc) : "l"(w), "l"(a))
#define PACK2(dst, lo, hi) asm("mov.b64 %0, {%1, %2};" : "=l"(dst) : "f"(lo), "f"(hi))
#define UNPACK2(lo, hi, src) asm("mov.b64 {%0, %1}, %2;" : "=f"(lo), "=f"(hi) : "l"(src))
#define CP_ASYNC16(saddr, gptr) \
    asm volatile("cp.async.cg.shared.global [%0], [%1], 16;" :: "r"(saddr), "l"(gptr))
#define CP_COMMIT() asm volatile("cp.async.commit_group;")
#define CP_WAIT0() asm volatile("cp.async.wait_group 0;" ::: "memory")

__device__ __forceinline__ unsigned smem_u32(const void* p) {
    return (unsigned)__cvta_generic_to_shared(p);
}

// ---------------- device scratch ----------------
__device__ __align__(16) float g_h2[NP * 64];
__device__ __align__(16) __half2 g_Hr[(size_t)RR * NP * 64];
__device__ __align__(16) float g_es[RR * NP * 2];
__device__ __align__(16) float g_ed[RR * NP * 2];
__device__ __align__(16) __half g_Fh[(size_t)NN * 512];   // fp16 GAT outputs (gather->mlp)
__device__ __align__(16) float g_wa[16 * 64];
__device__ int g_deg[MM];           // zero at entry: zero-init first call, re-zeroed by k_scan3
__device__ int g_indptr[MM + 1];
__device__ int g_cursor[MM];
__device__ int g_nbr[2 * EE];
__device__ int g_blksum[64];
__device__ int g_blkoff[64];

// ---------------- CSR build ----------------
__global__ void k_hist(const int* __restrict__ ei, const float* __restrict__ ew) {
    int e = blockIdx.x * 256 + threadIdx.x;
    if (e >= EE) return;
    int s = ei[e];
    int d = ei[EE + e];
    float w = ew[e];
    if (w > 0.f) {
        atomicAdd(&g_deg[0 * NN + d], 1);
        atomicAdd(&g_deg[1 * NN + s], 1);
    } else if (w < 0.f) {
        atomicAdd(&g_deg[2 * NN + d], 1);
        atomicAdd(&g_deg[3 * NN + s], 1);
    }
}

__global__ void k_scan1() {
    __shared__ int sd[512];
    int t = threadIdx.x;
    int base = blockIdx.x * 4096 + t * 8;
    int v[8];
    int s = 0;
#pragma unroll
    for (int i = 0; i < 8; i++) {
        int idx = base + i;
        int x = (idx < MM) ? g_deg[idx] : 0;
        v[i] = s;
        s += x;
    }
    sd[t] = s;
    __syncthreads();
    int tot = s;
    for (int off = 1; off < 512; off <<= 1) {
        int y = (t >= off) ? sd[t - off] : 0;
        __syncthreads();
        sd[t] += y;
        __syncthreads();
    }
    int excl = sd[t] - tot;
#pragma unroll
    for (int i = 0; i < 8; i++) {
        int idx = base + i;
        if (idx < MM) g_indptr[idx] = excl + v[i];
    }
    if (t == 511) g_blksum[blockIdx.x] = sd[511];
}

__global__ void k_scan2(int nblk) {
    int lane = threadIdx.x;
    int v0 = (lane < nblk) ? g_blksum[lane] : 0;
    int v1 = (32 + lane < nblk) ? g_blksum[32 + lane] : 0;
    int s0 = v0;
#pragma unroll
    for (int off = 1; off < 32; off <<= 1) {
        int t = __shfl_up_sync(0xffffffffu, s0, off);
        if (lane >= off) s0 += t;
    }
    int tot0 = __shfl_sync(0xffffffffu, s0, 31);
    int s1 = v1;
#pragma unroll
    for (int off = 1; off < 32; off <<= 1) {
        int t = __shfl_up_sync(0xffffffffu, s1, off);
        if (lane >= off) s1 += t;
    }
    s1 += tot0;
    if (lane < nblk) g_blkoff[lane] = s0 - v0;
    if (32 + lane < nblk) g_blkoff[32 + lane] = s1 - v1;
    if (lane == 31) g_indptr[MM] = s1;
}

__global__ void k_scan3() {
    int off = g_blkoff[blockIdx.x];
    int idx = blockIdx.x * 4096 + threadIdx.x;
#pragma unroll
    for (int i = 0; i < 8; i++, idx += 512) {
        if (idx < MM) {
            int val = g_indptr[idx] + off;
            g_indptr[idx] = val;
            g_cursor[idx] = val;
            g_deg[idx] = 0;          // restore invariant for next call
        }
    }
}

__global__ void k_scatter(const int* __restrict__ ei, const float* __restrict__ ew) {
    int e = blockIdx.x * 256 + threadIdx.x;
    if (e >= EE) return;
    int s = ei[e];
    int d = ei[EE + e];
    float w = ew[e];
    if (w > 0.f) {
        int p0 = atomicAdd(&g_cursor[0 * NN + d], 1); g_nbr[p0] = s;
        int p1 = atomicAdd(&g_cursor[1 * NN + s], 1); g_nbr[p1] = d;
    } else if (w < 0.f) {
        int p2 = atomicAdd(&g_cursor[2 * NN + d], 1); g_nbr[p2] = s;
        int p3 = atomicAdd(&g_cursor[3 * NN + s], 1); g_nbr[p3] = d;
    }
}

// ---------------- wa = W @ a ----------------
__global__ void k_wa(const float* __restrict__ W,
                     const float* __restrict__ asrc,
                     const float* __restrict__ adst, int l) {
    __shared__ float as_[64];
    int o = blockIdx.x;
    int r = o >> 2, sdm = (o >> 1) & 1, hd = o & 1;
    const float* a = (sdm ? adst : asrc) + ((size_t)(l * RR + r) * 2 + hd) * 64;
    int tid = threadIdx.x;
    if (tid < 64) as_[tid] = a[tid];
    __syncthreads();
    int w = tid >> 5, lane = tid & 31;
    float a0 = as_[lane], a1 = as_[lane + 32];
    for (int kk = 0; kk < 32; kk++) {
        int k = w * 32 + kk;
        const float* Wrow = W + ((size_t)(l * RR + r) * 64 + k) * 128 + hd * 64;
        float s = Wrow[lane] * a0 + Wrow[lane + 32] * a1;
#pragma unroll
        for (int o2 = 16; o2; o2 >>= 1) s += __shfl_down_sync(0xffffffffu, s, o2);
        if (lane == 0) g_wa[o * 64 + k] = s;
    }
}

// ---------------- attention logits ----------------
__global__ void k_logits(const float* __restrict__ xin, int l, int useX) {
    __shared__ float hs[16 * 65];
    __shared__ float was[16 * 65];
    const float* hin = useX ? xin : g_h2;
    int tid = threadIdx.x;
    int n0 = blockIdx.x * 16;
    for (int t = tid; t < 16 * 64; t += 256) {
        int nn = t >> 6, k = t & 63;
        hs[nn * 65 + k] = hin[(size_t)(n0 + nn) * 64 + k];
        was[nn * 65 + k] = g_wa[t];
    }
    __syncthreads();
    int o = tid & 15;
    int nn = tid >> 4;
    const float* hrow = hs + nn * 65;
    const float* wrow = was + o * 65;
    float s = 0.f;
#pragma unroll 8
    for (int k = 0; k < 64; k++) s += hrow[k] * wrow[k];
    int r = o >> 2, sdm = (o >> 1) & 1, hd = o & 1;
    float* dst = (sdm ? g_ed : g_es) + ((size_t)r * NP + n0 + nn) * 2 + hd;
    *dst = s;
}

// ---------------- per-relation feature GEMM: cp.async W fill, 4 cols x 16 nodes / thread ----------------
__global__ __launch_bounds__(128) void k_feat(const float* __restrict__ xin,
                                              const float* __restrict__ W,
                                              int l, int useX) {
    __shared__ __align__(16) float Ws[64 * 128];
    __shared__ __align__(16) float hsT[64 * 68];

    const float* hin = useX ? xin : g_h2;
    const int t = threadIdx.x;
    const int r = blockIdx.y;
    const int jc = t & 31;
    const int half = t >> 5;
    const float* Wp = W + (size_t)(l * RR + r) * 64 * 128;

    // async W fill (straight copy) overlapping the hsT transpose fill below
    unsigned s_Ws = smem_u32(Ws);
#pragma unroll
    for (int i = 0; i < 16; i++) {
        int c4 = t + i * 128;               // 0..2047 16B chunks
        CP_ASYNC16(s_Ws + c4 * 16, Wp + c4 * 4);
    }
    CP_COMMIT();

    int n0 = blockIdx.x * 64;
    for (int q = t; q < 64 * 64; q += 128) {
        int nn = q >> 6, k = q & 63;
        int n = n0 + nn;
        hsT[k * 68 + nn] = (n < NN) ? hin[(size_t)n * 64 + k] : 0.f;
    }
    CP_WAIT0();
    __syncthreads();

    unsigned long long acc[4][8];
#pragma unroll
    for (int c = 0; c < 4; c++)
#pragma unroll
        for (int p = 0; p < 8; p++) acc[c][p] = 0ull;

#pragma unroll 2
    for (int k = 0; k < 64; k++) {
        float w0 = Ws[k * 128 + jc];
        float w1 = Ws[k * 128 + jc + 32];
        float w2 = Ws[k * 128 + jc + 64];
        float w3 = Ws[k * 128 + jc + 96];
        unsigned long long wp0, wp1, wp2, wp3;
        PACK2(wp0, w0, w0); PACK2(wp1, w1, w1);
        PACK2(wp2, w2, w2); PACK2(wp3, w3, w3);
        const ulonglong2* hp = (const ulonglong2*)&hsT[k * 68 + half * 16];
#pragma unroll
        for (int q = 0; q < 4; q++) {
            ulonglong2 a = hp[q];
            FMA2(acc[0][2 * q], wp0, a.x); FMA2(acc[0][2 * q + 1], wp0, a.y);
            FMA2(acc[1][2 * q], wp1, a.x); FMA2(acc[1][2 * q + 1], wp1, a.y);
            FMA2(acc[2][2 * q], wp2, a.x); FMA2(acc[2][2 * q + 1], wp2, a.y);
            FMA2(acc[3][2 * q], wp3, a.x); FMA2(acc[3][2 * q + 1], wp3, a.y);
        }
    }
    __half2* Hrow = g_Hr + (size_t)r * NP * 64;
    int nb = n0 + half * 16;
#pragma unroll
    for (int p = 0; p < 8; p++) {
        float l0, h0, l1, h1, l2, h2, l3, h3;
        UNPACK2(l0, h0, acc[0][p]);
        UNPACK2(l1, h1, acc[1][p]);
        UNPACK2(l2, h2, acc[2][p]);
        UNPACK2(l3, h3, acc[3][p]);
        Hrow[(size_t)(nb + 2 * p) * 64 + jc]          = __floats2half2_rn(l0, l1);
        Hrow[(size_t)(nb + 2 * p + 1) * 64 + jc]      = __floats2half2_rn(h0, h1);
        Hrow[(size_t)(nb + 2 * p) * 64 + 32 + jc]     = __floats2half2_rn(l2, l3);
        Hrow[(size_t)(nb + 2 * p + 1) * 64 + 32 + jc] = __floats2half2_rn(h2, h3);
    }
}

// ---------------- CSR gather (round-11 structure, fp16 F output) ----------------
__global__ void k_gather(const float* __restrict__ gbias, int l) {
    int gw = (blockIdx.x * 256 + threadIdx.x) >> 5;
    int lane = threadIdx.x & 31;
    if (gw >= MM) return;
    int r = gw / NN;
    int d = gw - r * NN;
    int hd = lane >> 4;
    int cbase = hd * 64 + 2 * (lane & 15);

    const float* esr = g_es + (size_t)r * NP * 2;
    const float* edr = g_ed + (size_t)r * NP * 2;
    float edv = edr[d * 2 + hd];

    float e0 = esr[d * 2 + hd] + edv;
    e0 = fmaxf(e0, 0.2f * e0);
    float p = __expf(e0);
    const uint2* Hp = (const uint2*)(g_Hr + (size_t)r * NP * 64);
    uint2 sv = Hp[(size_t)d * 32 + lane];
    float2 f0 = __half22float2(*(__half2*)&sv.x);
    float2 f1 = __half22float2(*(__half2*)&sv.y);
    float a0 = p * f0.x, a1 = p * f1.x, a2 = p * f0.y, a3 = p * f1.y;
    float den = p;
    float b0 = 0.f, b1v = 0.f, b2v = 0.f, b3 = 0.f, denB = 0.f;

    int beg = g_indptr[gw];
    int end = g_indptr[gw + 1];
    int i = beg;
    for (; i + 2 <= end; i += 2) {
        int s0 = g_nbr[i];
        int s1 = g_nbr[i + 1];
        float ea = esr[s0 * 2 + hd] + edv;
        float eb = esr[s1 * 2 + hd] + edv;
        ea = fmaxf(ea, 0.2f * ea);
        eb = fmaxf(eb, 0.2f * eb);
        float pa = __expf(ea);
        float pb = __expf(eb);
        uint2 u0 = Hp[(size_t)s0 * 32 + lane];
        uint2 u1 = Hp[(size_t)s1 * 32 + lane];
        float2 g0 = __half22float2(*(__half2*)&u0.x);
        float2 g1 = __half22float2(*(__half2*)&u0.y);
        float2 h0 = __half22float2(*(__half2*)&u1.x);
        float2 h1 = __half22float2(*(__half2*)&u1.y);
        den += pa; denB += pb;
        a0 += pa * g0.x; a1 += pa * g1.x; a2 += pa * g0.y; a3 += pa * g1.y;
        b0 += pb * h0.x; b1v += pb * h1.x; b2v += pb * h0.y; b3 += pb * h1.y;
    }
    if (i < end) {
        int s0 = g_nbr[i];
        float ea = esr[s0 * 2 + hd] + edv;
        ea = fmaxf(ea, 0.2f * ea);
        float pa = __expf(ea);
        uint2 u0 = Hp[(size_t)s0 * 32 + lane];
        float2 g0 = __half22float2(*(__half2*)&u0.x);
        float2 g1 = __half22float2(*(__half2*)&u0.y);
        den += pa;
        a0 += pa * g0.x; a1 += pa * g1.x; a2 += pa * g0.y; a3 += pa * g1.y;
    }
    den += denB;
    a0 += b0; a1 += b1v; a2 += b2v; a3 += b3;

    float inv = 1.f / den;
    const float* bp = gbias + (size_t)(l * RR + r) * 128 + cbase;
    __half2* Fd = (__half2*)(g_Fh + (size_t)d * 512 + r * 128 + cbase);
    Fd[0]  = __floats2half2_rn(a0 * inv + bp[0], a1 * inv + bp[1]);
    Fd[16] = __floats2half2_rn(a2 * inv + bp[32], a3 * inv + bp[33]);
}

// ---------------- MLP + residual + LayerNorm: cp.async double-buffered, fp16 F in ----------------
__global__ __launch_bounds__(128) void k_mlp(const float* __restrict__ xin,
                      const float* __restrict__ W1,
                      const float* __restrict__ b1,
                      const float* __restrict__ W2,
                      const float* __restrict__ b2,
                      const float* __restrict__ lng,
                      const float* __restrict__ lnb,
                      int l, float* __restrict__ outbuf, int isLast, int useX) {
    extern __shared__ __align__(16) float sm[];
    float* scomb = sm;                        // 16*576 = 9216 floats
    float* wbuf0 = scomb + 16 * 576;          // 4096
    float* wbuf1 = wbuf0 + 4096;              // 4096
    float* sRed = wbuf1 + 4096;               // 64

    const float* hin = useX ? xin : g_h2;
    float* hout = isLast ? outbuf : g_h2;

    int tid = threadIdx.x;
    int j = tid & 63;
    int g = tid >> 6;
    int lane = tid & 31;
    int w2 = (tid >> 5) & 1;
    int n0 = blockIdx.x * 16;

    const float* W1p = W1 + (size_t)l * 576 * 64;
    const float* W2p = W2 + (size_t)l * 4096;

    unsigned s_scomb = smem_u32(scomb);
    unsigned s_w0 = smem_u32(wbuf0);

#pragma unroll
    for (int i = 0; i < 2; i++) {
        int c4 = tid + i * 128;
        int nn = c4 >> 4, k4 = c4 & 15;
        CP_ASYNC16(s_scomb + (nn * 576 + k4 * 4) * 4,
                   hin + (size_t)(n0 + nn) * 64 + k4 * 4);
    }
#pragma unroll
    for (int i = 0; i < 8; i++) {
        int c4 = tid + i * 128;
        CP_ASYNC16(s_w0 + c4 * 16, W1p + c4 * 4);
    }
    CP_COMMIT();

#pragma unroll
    for (int i = 0; i < 16; i++) {
        int c = tid + i * 128;
        int nn = c >> 7, k4 = c & 127;
        uint2 raw = *(const uint2*)(g_Fh + (size_t)(n0 + nn) * 512 + k4 * 4);
        float2 f0 = __half22float2(*(__half2*)&raw.x);
        float2 f1 = __half22float2(*(__half2*)&raw.y);
        *(float4*)(scomb + nn * 576 + 64 + k4 * 4) = make_float4(f0.x, f0.y, f1.x, f1.y);
    }
    CP_WAIT0();
    __syncthreads();

    unsigned long long accA[8], accB[8];
#pragma unroll
    for (int n = 0; n < 8; n++) { accA[n] = 0ull; accB[n] = 0ull; }

    for (int kt = 0; kt < 9; kt++) {
        const float* nxt = (kt < 8) ? (W1p + (kt + 1) * 4096) : W2p;
        unsigned dstb = (kt & 1) ? s_w0 : smem_u32(wbuf1);
#pragma unroll
        for (int i = 0; i < 8; i++) {
            int c4 = tid + i * 128;
            CP_ASYNC16(dstb + c4 * 16, nxt + c4 * 4);
        }
        CP_COMMIT();

        const float* Wt = (kt & 1) ? wbuf1 : wbuf0;
#pragma unroll 4
        for (int kk4 = 0; kk4 < 16; kk4++) {
            float w0 = Wt[(kk4 * 4 + 0) * 64 + j];
            float w1 = Wt[(kk4 * 4 + 1) * 64 + j];
            float w2f = Wt[(kk4 * 4 + 2) * 64 + j];
            float w3 = Wt[(kk4 * 4 + 3) * 64 + j];
            unsigned long long wp01, wp23;
            PACK2(wp01, w0, w1);
            PACK2(wp23, w2f, w3);
#pragma unroll
            for (int n = 0; n < 8; n++) {
                ulonglong2 a = ((const ulonglong2*)(scomb + (g * 8 + n) * 576))[kt * 16 + kk4];
                FMA2(accA[n], wp01, a.x);
                FMA2(accB[n], wp23, a.y);
            }
        }
        CP_WAIT0();
        __syncthreads();
    }

    float bb = b1[l * 64 + j];
#pragma unroll
    for (int n = 0; n < 8; n++) {
        float lo, hi, lo2, hi2;
        UNPACK2(lo, hi, accA[n]);
        UNPACK2(lo2, hi2, accB[n]);
        scomb[(g * 8 + n) * 576 + 64 + j] = tanhf(bb + lo + hi + lo2 + hi2);
    }
    __syncthreads();

    const float* Wt2 = wbuf1;
    unsigned long long zA[8], zB[8];
#pragma unroll
    for (int n = 0; n < 8; n++) { zA[n] = 0ull; zB[n] = 0ull; }
#pragma unroll 4
    for (int kk4 = 0; kk4 < 16; kk4++) {
        float w0 = Wt2[(kk4 * 4 + 0) * 64 + j];
        float w1 = Wt2[(kk4 * 4 + 1) * 64 + j];
        float w2f = Wt2[(kk4 * 4 + 2) * 64 + j];
        float w3 = Wt2[(kk4 * 4 + 3) * 64 + j];
        unsigned long long wp01, wp23;
        PACK2(wp01, w0, w1);
        PACK2(wp23, w2f, w3);
#pragma unroll
        for (int n = 0; n < 8; n++) {
            ulonglong2 a = ((const ulonglong2*)(scomb + (g * 8 + n) * 576 + 64))[kk4];
            FMA2(zA[n], wp01, a.x);
            FMA2(zB[n], wp23, a.y);
        }
    }
    float z[8];
    float bb2 = b2[l * 64 + j];
#pragma unroll
    for (int n = 0; n < 8; n++) {
        float lo, hi, lo2, hi2;
        UNPACK2(lo, hi, zA[n]);
        UNPACK2(lo2, hi2, zB[n]);
        z[n] = bb2 + lo + hi + lo2 + hi2 + scomb[(g * 8 + n) * 576 + j];
    }

#pragma unroll
    for (int n = 0; n < 8; n++) {
        float a = z[n], bsq = z[n] * z[n];
#pragma unroll
        for (int o = 16; o; o >>= 1) {
            a += __shfl_down_sync(0xffffffffu, a, o);
            bsq += __shfl_down_sync(0xffffffffu, bsq, o);
        }
        if (lane == 0) {
            sRed[((g * 2 + w2) * 8 + n) * 2 + 0] = a;
            sRed[((g * 2 + w2) * 8 + n) * 2 + 1] = bsq;
        }
    }
    __syncthreads();

    float gj = lng[l * 64 + j];
    float bj = lnb[l * 64 + j];
#pragma unroll
    for (int n = 0; n < 8; n++) {
        float su = sRed[((g * 2 + 0) * 8 + n) * 2 + 0] + sRed[((g * 2 + 1) * 8 + n) * 2 + 0];
        float sq = sRed[((g * 2 + 0) * 8 + n) * 2 + 1] + sRed[((g * 2 + 1) * 8 + n) * 2 + 1];
        float mu = su * (1.f / 64.f);
        float var = sq * (1.f / 64.f) - mu * mu;
        float nrm = rsqrtf(var + 1e-5f);
        int n_ = n0 + g * 8 + n;
        hout[(size_t)n_ * 64 + j] = (z[n] - mu) * nrm * gj + bj;
    }
}

// ---------------- launch ----------------
extern "C" void kernel_launch(void* const* d_in, const int* in_sizes, int n_in,
                              void* d_out, int out_size) {
    const float* x   = (const float*)d_in[0];
    const int*   ei  = (const int*)d_in[1];
    const float* ew  = (const float*)d_in[2];
    const float* gW  = (const float*)d_in[3];
    const float* gas = (const float*)d_in[4];
    const float* gad = (const float*)d_in[5];
    const float* gb  = (const float*)d_in[6];
    const float* W1  = (const float*)d_in[7];
    const float* b1  = (const float*)d_in[8];
    const float* W2  = (const float*)d_in[9];
    const float* b2  = (const float*)d_in[10];
    const float* lg  = (const float*)d_in[11];
    const float* lb  = (const float*)d_in[12];
    float* out = (float*)d_out;

    const int mlp_smem = (16 * 576 + 4096 + 4096 + 64) * 4;   // 69888 B
    cudaFuncSetAttribute(k_mlp, cudaFuncAttributeMaxDynamicSharedMemorySize, mlp_smem);

    k_wa<<<16, 64>>>(gW, gas, gad, 0);
    k_logits<<<NN / 16, 256>>>(x, 0, 1);
    k_feat<<<dim3((NP + 63) / 64, RR), 128>>>(x, gW, 0, 1);
    k_hist<<<(EE + 255) / 256, 256>>>(ei, ew);
    k_scan1<<<SCAN_BLOCKS, 512>>>();
    k_scan2<<<1, 32>>>(SCAN_BLOCKS);
    k_scan3<<<SCAN_BLOCKS, 512>>>();
    k_scatter<<<(EE + 255) / 256, 256>>>(ei, ew);

    k_gather<<<MM / 8, 256>>>(gb, 0);
    k_mlp<<<NN / 16, 128, mlp_smem>>>(x, W1, b1, W2, b2, lg, lb, 0, out, 0, 1);

    // layer 1
    k_wa<<<16, 64>>>(gW, gas, gad, 1);
    k_logits<<<NN / 16, 256>>>(x, 1, 0);
    k_feat<<<dim3((NP + 63) / 64, RR), 128>>>(x, gW, 1, 0);
    k_gather<<<MM / 8, 256>>>(gb, 1);
    k_mlp<<<NN / 16, 128, mlp_smem>>>(x, W1, b1, W2, b2, lg, lb, 1, out, 1, 0);
}

// round 15
// speedup vs baseline: 1.0864x; 1.0291x over previous
#include <cuda_runtime.h>
#include <cuda_fp16.h>
#include <math.h>

#define NN 50000
#define NP 50048
#define EE 400000
#define RR 4
#define MM (RR*NN)
#define SCAN_BLOCKS ((MM + 4095) / 4096)   // 49

#define FMA2(acc, w, a) asm("fma.rn.f32x2 %0, %1, %2, %0;" : "+l"(acc) : "l"(w), "l"(a))
#define PACK2(dst, lo, hi) asm("mov.b64 %0, {%1, %2};" : "=l"(dst) : "f"(lo), "f"(hi))
#define UNPACK2(lo, hi, src) asm("mov.b64 {%0, %1}, %2;" : "=f"(lo), "=f"(hi) : "l"(src))
#define CP_ASYNC16(saddr, gptr) \
    asm volatile("cp.async.cg.shared.global [%0], [%1], 16;" :: "r"(saddr), "l"(gptr))
#define CP_COMMIT() asm volatile("cp.async.commit_group;")
#define CP_WAIT0() asm volatile("cp.async.wait_group 0;" ::: "memory")

__device__ __forceinline__ unsigned smem_u32(const void* p) {
    return (unsigned)__cvta_generic_to_shared(p);
}

// ---------------- device scratch ----------------
__device__ __align__(16) float g_h2[NP * 64];
__device__ __align__(16) __half2 g_Hr[(size_t)RR * NP * 64];
__device__ __align__(16) float g_es[RR * NP * 2];
__device__ __align__(16) float g_ed[RR * NP * 2];
__device__ __align__(16) __half g_Fh[(size_t)NN * 512];   // fp16 GAT outputs (gather->mlp)
__device__ __align__(16) float g_wa[16 * 64];
__device__ int g_deg[MM];           // zero at entry: zero-init first call, re-zeroed by k_scan3
__device__ int g_indptr[MM + 1];
__device__ int g_cursor[MM];
__device__ int g_nbr[2 * EE];
__device__ int g_blksum[64];
__device__ int g_blkoff[64];

// ---------------- CSR build ----------------
__global__ void k_hist(const int* __restrict__ ei, const float* __restrict__ ew) {
    int e = blockIdx.x * 256 + threadIdx.x;
    if (e >= EE) return;
    int s = ei[e];
    int d = ei[EE + e];
    float w = ew[e];
    if (w > 0.f) {
        atomicAdd(&g_deg[0 * NN + d], 1);
        atomicAdd(&g_deg[1 * NN + s], 1);
    } else if (w < 0.f) {
        atomicAdd(&g_deg[2 * NN + d], 1);
        atomicAdd(&g_deg[3 * NN + s], 1);
    }
}

__global__ void k_scan1() {
    __shared__ int sd[512];
    int t = threadIdx.x;
    int base = blockIdx.x * 4096 + t * 8;
    int v[8];
    int s = 0;
#pragma unroll
    for (int i = 0; i < 8; i++) {
        int idx = base + i;
        int x = (idx < MM) ? g_deg[idx] : 0;
        v[i] = s;
        s += x;
    }
    sd[t] = s;
    __syncthreads();
    int tot = s;
    for (int off = 1; off < 512; off <<= 1) {
        int y = (t >= off) ? sd[t - off] : 0;
        __syncthreads();
        sd[t] += y;
        __syncthreads();
    }
    int excl = sd[t] - tot;
#pragma unroll
    for (int i = 0; i < 8; i++) {
        int idx = base + i;
        if (idx < MM) g_indptr[idx] = excl + v[i];
    }
    if (t == 511) g_blksum[blockIdx.x] = sd[511];
}

__global__ void k_scan2(int nblk) {
    int lane = threadIdx.x;
    int v0 = (lane < nblk) ? g_blksum[lane] : 0;
    int v1 = (32 + lane < nblk) ? g_blksum[32 + lane] : 0;
    int s0 = v0;
#pragma unroll
    for (int off = 1; off < 32; off <<= 1) {
        int t = __shfl_up_sync(0xffffffffu, s0, off);
        if (lane >= off) s0 += t;
    }
    int tot0 = __shfl_sync(0xffffffffu, s0, 31);
    int s1 = v1;
#pragma unroll
    for (int off = 1; off < 32; off <<= 1) {
        int t = __shfl_up_sync(0xffffffffu, s1, off);
        if (lane >= off) s1 += t;
    }
    s1 += tot0;
    if (lane < nblk) g_blkoff[lane] = s0 - v0;
    if (32 + lane < nblk) g_blkoff[32 + lane] = s1 - v1;
    if (lane == 31) g_indptr[MM] = s1;
}

__global__ void k_scan3() {
    int off = g_blkoff[blockIdx.x];
    int idx = blockIdx.x * 4096 + threadIdx.x;
#pragma unroll
    for (int i = 0; i < 8; i++, idx += 512) {
        if (idx < MM) {
            int val = g_indptr[idx] + off;
            g_indptr[idx] = val;
            g_cursor[idx] = val;
            g_deg[idx] = 0;          // restore invariant for next call
        }
    }
}

__global__ void k_scatter(const int* __restrict__ ei, const float* __restrict__ ew) {
    int e = blockIdx.x * 256 + threadIdx.x;
    if (e >= EE) return;
    int s = ei[e];
    int d = ei[EE + e];
    float w = ew[e];
    if (w > 0.f) {
        int p0 = atomicAdd(&g_cursor[0 * NN + d], 1); g_nbr[p0] = s;
        int p1 = atomicAdd(&g_cursor[1 * NN + s], 1); g_nbr[p1] = d;
    } else if (w < 0.f) {
        int p2 = atomicAdd(&g_cursor[2 * NN + d], 1); g_nbr[p2] = s;
        int p3 = atomicAdd(&g_cursor[3 * NN + s], 1); g_nbr[p3] = d;
    }
}

// ---------------- wa = W @ a ----------------
__global__ void k_wa(const float* __restrict__ W,
                     const float* __restrict__ asrc,
                     const float* __restrict__ adst, int l) {
    __shared__ float as_[64];
    int o = blockIdx.x;
    int r = o >> 2, sdm = (o >> 1) & 1, hd = o & 1;
    const float* a = (sdm ? adst : asrc) + ((size_t)(l * RR + r) * 2 + hd) * 64;
    int tid = threadIdx.x;
    if (tid < 64) as_[tid] = a[tid];
    __syncthreads();
    int w = tid >> 5, lane = tid & 31;
    float a0 = as_[lane], a1 = as_[lane + 32];
    for (int kk = 0; kk < 32; kk++) {
        int k = w * 32 + kk;
        const float* Wrow = W + ((size_t)(l * RR + r) * 64 + k) * 128 + hd * 64;
        float s = Wrow[lane] * a0 + Wrow[lane + 32] * a1;
#pragma unroll
        for (int o2 = 16; o2; o2 >>= 1) s += __shfl_down_sync(0xffffffffu, s, o2);
        if (lane == 0) g_wa[o * 64 + k] = s;
    }
}

// ---------------- attention logits ----------------
__global__ void k_logits(const float* __restrict__ xin, int l, int useX) {
    __shared__ float hs[16 * 65];
    __shared__ float was[16 * 65];
    const float* hin = useX ? xin : g_h2;
    int tid = threadIdx.x;
    int n0 = blockIdx.x * 16;
    for (int t = tid; t < 16 * 64; t += 256) {
        int nn = t >> 6, k = t & 63;
        hs[nn * 65 + k] = hin[(size_t)(n0 + nn) * 64 + k];
        was[nn * 65 + k] = g_wa[t];
    }
    __syncthreads();
    int o = tid & 15;
    int nn = tid >> 4;
    const float* hrow = hs + nn * 65;
    const float* wrow = was + o * 65;
    float s = 0.f;
#pragma unroll 8
    for (int k = 0; k < 64; k++) s += hrow[k] * wrow[k];
    int r = o >> 2, sdm = (o >> 1) & 1, hd = o & 1;
    float* dst = (sdm ? g_ed : g_es) + ((size_t)r * NP + n0 + nn) * 2 + hd;
    *dst = s;
}

// ---------------- per-relation feature GEMM: cp.async W fill, 4 cols x 16 nodes / thread ----------------
__global__ __launch_bounds__(128) void k_feat(const float* __restrict__ xin,
                                              const float* __restrict__ W,
                                              int l, int useX) {
    __shared__ __align__(16) float Ws[64 * 128];
    __shared__ __align__(16) float hsT[64 * 68];

    const float* hin = useX ? xin : g_h2;
    const int t = threadIdx.x;
    const int r = blockIdx.y;
    const int jc = t & 31;
    const int half = t >> 5;
    const float* Wp = W + (size_t)(l * RR + r) * 64 * 128;

    unsigned s_Ws = smem_u32(Ws);
#pragma unroll
    for (int i = 0; i < 16; i++) {
        int c4 = t + i * 128;
        CP_ASYNC16(s_Ws + c4 * 16, Wp + c4 * 4);
    }
    CP_COMMIT();

    int n0 = blockIdx.x * 64;
    for (int q = t; q < 64 * 64; q += 128) {
        int nn = q >> 6, k = q & 63;
        int n = n0 + nn;
        hsT[k * 68 + nn] = (n < NN) ? hin[(size_t)n * 64 + k] : 0.f;
    }
    CP_WAIT0();
    __syncthreads();

    unsigned long long acc[4][8];
#pragma unroll
    for (int c = 0; c < 4; c++)
#pragma unroll
        for (int p = 0; p < 8; p++) acc[c][p] = 0ull;

#pragma unroll 2
    for (int k = 0; k < 64; k++) {
        float w0 = Ws[k * 128 + jc];
        float w1 = Ws[k * 128 + jc + 32];
        float w2 = Ws[k * 128 + jc + 64];
        float w3 = Ws[k * 128 + jc + 96];
        unsigned long long wp0, wp1, wp2, wp3;
        PACK2(wp0, w0, w0); PACK2(wp1, w1, w1);
        PACK2(wp2, w2, w2); PACK2(wp3, w3, w3);
        const ulonglong2* hp = (const ulonglong2*)&hsT[k * 68 + half * 16];
#pragma unroll
        for (int q = 0; q < 4; q++) {
            ulonglong2 a = hp[q];
            FMA2(acc[0][2 * q], wp0, a.x); FMA2(acc[0][2 * q + 1], wp0, a.y);
            FMA2(acc[1][2 * q], wp1, a.x); FMA2(acc[1][2 * q + 1], wp1, a.y);
            FMA2(acc[2][2 * q], wp2, a.x); FMA2(acc[2][2 * q + 1], wp2, a.y);
            FMA2(acc[3][2 * q], wp3, a.x); FMA2(acc[3][2 * q + 1], wp3, a.y);
        }
    }
    __half2* Hrow = g_Hr + (size_t)r * NP * 64;
    int nb = n0 + half * 16;
#pragma unroll
    for (int p = 0; p < 8; p++) {
        float l0, h0, l1, h1, l2, h2, l3, h3;
        UNPACK2(l0, h0, acc[0][p]);
        UNPACK2(l1, h1, acc[1][p]);
        UNPACK2(l2, h2, acc[2][p]);
        UNPACK2(l3, h3, acc[3][p]);
        Hrow[(size_t)(nb + 2 * p) * 64 + jc]          = __floats2half2_rn(l0, l1);
        Hrow[(size_t)(nb + 2 * p + 1) * 64 + jc]      = __floats2half2_rn(h0, h1);
        Hrow[(size_t)(nb + 2 * p) * 64 + 32 + jc]     = __floats2half2_rn(l2, l3);
        Hrow[(size_t)(nb + 2 * p + 1) * 64 + 32 + jc] = __floats2half2_rn(h2, h3);
    }
}

// ---------------- CSR gather: 2 rows per warp, 16 lanes/row, uint4 H loads ----------------
// lane q (0..15) covers slots 4q..4q+3; canonical cols cbase..cbase+3 and cbase+32..+35
// with cbase = (q>>3)*64 + 4*(q&7).
__global__ void k_gather(const float* __restrict__ gbias, int l) {
    int warp = (blockIdx.x * 256 + threadIdx.x) >> 5;
    int lane = threadIdx.x & 31;
    int hw = lane >> 4;          // row within pair
    int q = lane & 15;           // lane within row
    int gw = warp * 2 + hw;
    if (gw >= MM) return;
    int r = gw / NN;
    int d = gw - r * NN;
    int hd = q >> 3;
    int cbase = hd * 64 + 4 * (q & 7);

    const float* esr = g_es + (size_t)r * NP * 2;
    float edv = g_ed[((size_t)r * NP + d) * 2 + hd];
    const uint4* Hp = (const uint4*)(g_Hr + (size_t)r * NP * 64);   // 16 uint4 per row

    // self loop
    float e0 = esr[d * 2 + hd] + edv;
    e0 = fmaxf(e0, 0.2f * e0);
    float p = __expf(e0);
    uint4 sv = Hp[(size_t)d * 16 + q];
    float2 f0 = __half22float2(*(__half2*)&sv.x);
    float2 f1 = __half22float2(*(__half2*)&sv.y);
    float2 f2 = __half22float2(*(__half2*)&sv.z);
    float2 f3 = __half22float2(*(__half2*)&sv.w);
    float a0 = p * f0.x, a4 = p * f0.y;
    float a1 = p * f1.x, a5 = p * f1.y;
    float a2 = p * f2.x, a6 = p * f2.y;
    float a3 = p * f3.x, a7 = p * f3.y;
    float den = p;
    float b0 = 0.f, b1 = 0.f, b2 = 0.f, b3 = 0.f;
    float b4 = 0.f, b5 = 0.f, b6 = 0.f, b7 = 0.f, denB = 0.f;

    int beg = g_indptr[gw];
    int end = g_indptr[gw + 1];
    int i = beg;
    for (; i + 2 <= end; i += 2) {
        int s0 = g_nbr[i];
        int s1 = g_nbr[i + 1];
        float ea = esr[s0 * 2 + hd] + edv;
        float eb = esr[s1 * 2 + hd] + edv;
        ea = fmaxf(ea, 0.2f * ea);
        eb = fmaxf(eb, 0.2f * eb);
        float pa = __expf(ea);
        float pb = __expf(eb);
        uint4 u0 = Hp[(size_t)s0 * 16 + q];
        uint4 u1 = Hp[(size_t)s1 * 16 + q];
        den += pa; denB += pb;
        float2 g0 = __half22float2(*(__half2*)&u0.x);
        float2 g1 = __half22float2(*(__half2*)&u0.y);
        float2 g2 = __half22float2(*(__half2*)&u0.z);
        float2 g3 = __half22float2(*(__half2*)&u0.w);
        a0 += pa * g0.x; a4 += pa * g0.y;
        a1 += pa * g1.x; a5 += pa * g1.y;
        a2 += pa * g2.x; a6 += pa * g2.y;
        a3 += pa * g3.x; a7 += pa * g3.y;
        float2 h0 = __half22float2(*(__half2*)&u1.x);
        float2 h1 = __half22float2(*(__half2*)&u1.y);
        float2 h2 = __half22float2(*(__half2*)&u1.z);
        float2 h3 = __half22float2(*(__half2*)&u1.w);
        b0 += pb * h0.x; b4 += pb * h0.y;
        b1 += pb * h1.x; b5 += pb * h1.y;
        b2 += pb * h2.x; b6 += pb * h2.y;
        b3 += pb * h3.x; b7 += pb * h3.y;
    }
    if (i < end) {
        int s0 = g_nbr[i];
        float ea = esr[s0 * 2 + hd] + edv;
        ea = fmaxf(ea, 0.2f * ea);
        float pa = __expf(ea);
        uint4 u0 = Hp[(size_t)s0 * 16 + q];
        den += pa;
        float2 g0 = __half22float2(*(__half2*)&u0.x);
        float2 g1 = __half22float2(*(__half2*)&u0.y);
        float2 g2 = __half22float2(*(__half2*)&u0.z);
        float2 g3 = __half22float2(*(__half2*)&u0.w);
        a0 += pa * g0.x; a4 += pa * g0.y;
        a1 += pa * g1.x; a5 += pa * g1.y;
        a2 += pa * g2.x; a6 += pa * g2.y;
        a3 += pa * g3.x; a7 += pa * g3.y;
    }
    den += denB;
    a0 += b0; a1 += b1; a2 += b2; a3 += b3;
    a4 += b4; a5 += b5; a6 += b6; a7 += b7;

    float inv = 1.f / den;
    const float* bp = gbias + (size_t)(l * RR + r) * 128 + cbase;
    // lo cols cbase..cbase+3; hi cols cbase+32..+35
    __half2 o0 = __floats2half2_rn(a0 * inv + bp[0], a1 * inv + bp[1]);
    __half2 o1 = __floats2half2_rn(a2 * inv + bp[2], a3 * inv + bp[3]);
    __half2 o2 = __floats2half2_rn(a4 * inv + bp[32], a5 * inv + bp[33]);
    __half2 o3 = __floats2half2_rn(a6 * inv + bp[34], a7 * inv + bp[35]);
    __half* Fd = g_Fh + (size_t)d * 512 + r * 128 + cbase;
    *(uint2*)Fd = make_uint2(*(unsigned*)&o0, *(unsigned*)&o1);
    *(uint2*)(Fd + 32) = make_uint2(*(unsigned*)&o2, *(unsigned*)&o3);
}

// ---------------- MLP + residual + LayerNorm: cp.async double-buffered, fp16 F in ----------------
__global__ __launch_bounds__(128) void k_mlp(const float* __restrict__ xin,
                      const float* __restrict__ W1,
                      const float* __restrict__ b1,
                      const float* __restrict__ W2,
                      const float* __restrict__ b2,
                      const float* __restrict__ lng,
                      const float* __restrict__ lnb,
                      int l, float* __restrict__ outbuf, int isLast, int useX) {
    extern __shared__ __align__(16) float sm[];
    float* scomb = sm;                        // 16*576 = 9216 floats
    float* wbuf0 = scomb + 16 * 576;          // 4096
    float* wbuf1 = wbuf0 + 4096;              // 4096
    float* sRed = wbuf1 + 4096;               // 64

    const float* hin = useX ? xin : g_h2;
    float* hout = isLast ? outbuf : g_h2;

    int tid = threadIdx.x;
    int j = tid & 63;
    int g = tid >> 6;
    int lane = tid & 31;
    int w2 = (tid >> 5) & 1;
    int n0 = blockIdx.x * 16;

    const float* W1p = W1 + (size_t)l * 576 * 64;
    const float* W2p = W2 + (size_t)l * 4096;

    unsigned s_scomb = smem_u32(scomb);
    unsigned s_w0 = smem_u32(wbuf0);

#pragma unroll
    for (int i = 0; i < 2; i++) {
        int c4 = tid + i * 128;
        int nn = c4 >> 4, k4 = c4 & 15;
        CP_ASYNC16(s_scomb + (nn * 576 + k4 * 4) * 4,
                   hin + (size_t)(n0 + nn) * 64 + k4 * 4);
    }
#pragma unroll
    for (int i = 0; i < 8; i++) {
        int c4 = tid + i * 128;
        CP_ASYNC16(s_w0 + c4 * 16, W1p + c4 * 4);
    }
    CP_COMMIT();

#pragma unroll
    for (int i = 0; i < 16; i++) {
        int c = tid + i * 128;
        int nn = c >> 7, k4 = c & 127;
        uint2 raw = *(const uint2*)(g_Fh + (size_t)(n0 + nn) * 512 + k4 * 4);
        float2 f0 = __half22float2(*(__half2*)&raw.x);
        float2 f1 = __half22float2(*(__half2*)&raw.y);
        *(float4*)(scomb + nn * 576 + 64 + k4 * 4) = make_float4(f0.x, f0.y, f1.x, f1.y);
    }
    CP_WAIT0();
    __syncthreads();

    unsigned long long accA[8], accB[8];
#pragma unroll
    for (int n = 0; n < 8; n++) { accA[n] = 0ull; accB[n] = 0ull; }

    for (int kt = 0; kt < 9; kt++) {
        const float* nxt = (kt < 8) ? (W1p + (kt + 1) * 4096) : W2p;
        unsigned dstb = (kt & 1) ? s_w0 : smem_u32(wbuf1);
#pragma unroll
        for (int i = 0; i < 8; i++) {
            int c4 = tid + i * 128;
            CP_ASYNC16(dstb + c4 * 16, nxt + c4 * 4);
        }
        CP_COMMIT();

        const float* Wt = (kt & 1) ? wbuf1 : wbuf0;
#pragma unroll 4
        for (int kk4 = 0; kk4 < 16; kk4++) {
            float w0 = Wt[(kk4 * 4 + 0) * 64 + j];
            float w1 = Wt[(kk4 * 4 + 1) * 64 + j];
            float w2f = Wt[(kk4 * 4 + 2) * 64 + j];
            float w3 = Wt[(kk4 * 4 + 3) * 64 + j];
            unsigned long long wp01, wp23;
            PACK2(wp01, w0, w1);
            PACK2(wp23, w2f, w3);
#pragma unroll
            for (int n = 0; n < 8; n++) {
                ulonglong2 a = ((const ulonglong2*)(scomb + (g * 8 + n) * 576))[kt * 16 + kk4];
                FMA2(accA[n], wp01, a.x);
                FMA2(accB[n], wp23, a.y);
            }
        }
        CP_WAIT0();
        __syncthreads();
    }

    float bb = b1[l * 64 + j];
#pragma unroll
    for (int n = 0; n < 8; n++) {
        float lo, hi, lo2, hi2;
        UNPACK2(lo, hi, accA[n]);
        UNPACK2(lo2, hi2, accB[n]);
        scomb[(g * 8 + n) * 576 + 64 + j] = tanhf(bb + lo + hi + lo2 + hi2);
    }
    __syncthreads();

    const float* Wt2 = wbuf1;
    unsigned long long zA[8], zB[8];
#pragma unroll
    for (int n = 0; n < 8; n++) { zA[n] = 0ull; zB[n] = 0ull; }
#pragma unroll 4
    for (int kk4 = 0; kk4 < 16; kk4++) {
        float w0 = Wt2[(kk4 * 4 + 0) * 64 + j];
        float w1 = Wt2[(kk4 * 4 + 1) * 64 + j];
        float w2f = Wt2[(kk4 * 4 + 2) * 64 + j];
        float w3 = Wt2[(kk4 * 4 + 3) * 64 + j];
        unsigned long long wp01, wp23;
        PACK2(wp01, w0, w1);
        PACK2(wp23, w2f, w3);
#pragma unroll
        for (int n = 0; n < 8; n++) {
            ulonglong2 a = ((const ulonglong2*)(scomb + (g * 8 + n) * 576 + 64))[kk4];
            FMA2(zA[n], wp01, a.x);
            FMA2(zB[n], wp23, a.y);
        }
    }
    float z[8];
    float bb2 = b2[l * 64 + j];
#pragma unroll
    for (int n = 0; n < 8; n++) {
        float lo, hi, lo2, hi2;
        UNPACK2(lo, hi, zA[n]);
        UNPACK2(lo2, hi2, zB[n]);
        z[n] = bb2 + lo + hi + lo2 + hi2 + scomb[(g * 8 + n) * 576 + j];
    }

#pragma unroll
    for (int n = 0; n < 8; n++) {
        float a = z[n], bsq = z[n] * z[n];
#pragma unroll
        for (int o = 16; o; o >>= 1) {
            a += __shfl_down_sync(0xffffffffu, a, o);
            bsq += __shfl_down_sync(0xffffffffu, bsq, o);
        }
        if (lane == 0) {
            sRed[((g * 2 + w2) * 8 + n) * 2 + 0] = a;
            sRed[((g * 2 + w2) * 8 + n) * 2 + 1] = bsq;
        }
    }
    __syncthreads();

    float gj = lng[l * 64 + j];
    float bj = lnb[l * 64 + j];
#pragma unroll
    for (int n = 0; n < 8; n++) {
        float su = sRed[((g * 2 + 0) * 8 + n) * 2 + 0] + sRed[((g * 2 + 1) * 8 + n) * 2 + 0];
        float sq = sRed[((g * 2 + 0) * 8 + n) * 2 + 1] + sRed[((g * 2 + 1) * 8 + n) * 2 + 1];
        float mu = su * (1.f / 64.f);
        float var = sq * (1.f / 64.f) - mu * mu;
        float nrm = rsqrtf(var + 1e-5f);
        int n_ = n0 + g * 8 + n;
        hout[(size_t)n_ * 64 + j] = (z[n] - mu) * nrm * gj + bj;
    }
}

// ---------------- launch ----------------
extern "C" void kernel_launch(void* const* d_in, const int* in_sizes, int n_in,
                              void* d_out, int out_size) {
    const float* x   = (const float*)d_in[0];
    const int*   ei  = (const int*)d_in[1];
    const float* ew  = (const float*)d_in[2];
    const float* gW  = (const float*)d_in[3];
    const float* gas = (const float*)d_in[4];
    const float* gad = (const float*)d_in[5];
    const float* gb  = (const float*)d_in[6];
    const float* W1  = (const float*)d_in[7];
    const float* b1  = (const float*)d_in[8];
    const float* W2  = (const float*)d_in[9];
    const float* b2  = (const float*)d_in[10];
    const float* lg  = (const float*)d_in[11];
    const float* lb  = (const float*)d_in[12];
    float* out = (float*)d_out;

    const int mlp_smem = (16 * 576 + 4096 + 4096 + 64) * 4;   // 69888 B
    cudaFuncSetAttribute(k_mlp, cudaFuncAttributeMaxDynamicSharedMemorySize, mlp_smem);

    k_wa<<<16, 64>>>(gW, gas, gad, 0);
    k_logits<<<NN / 16, 256>>>(x, 0, 1);
    k_feat<<<dim3((NP + 63) / 64, RR), 128>>>(x, gW, 0, 1);
    k_hist<<<(EE + 255) / 256, 256>>>(ei, ew);
    k_scan1<<<SCAN_BLOCKS, 512>>>();
    k_scan2<<<1, 32>>>(SCAN_BLOCKS);
    k_scan3<<<SCAN_BLOCKS, 512>>>();
    k_scatter<<<(EE + 255) / 256, 256>>>(ei, ew);

    k_gather<<<MM / 16, 256>>>(gb, 0);
    k_mlp<<<NN / 16, 128, mlp_smem>>>(x, W1, b1, W2, b2, lg, lb, 0, out, 0, 1);

    // layer 1
    k_wa<<<16, 64>>>(gW, gas, gad, 1);
    k_logits<<<NN / 16, 256>>>(x, 1, 0);
    k_feat<<<dim3((NP + 63) / 64, RR), 128>>>(x, gW, 1, 0);
    k_gather<<<MM / 16, 256>>>(gb, 1);
    k_mlp<<<NN / 16, 128, mlp_smem>>>(x, W1, b1, W2, b2, lg, lb, 1, out, 1, 0);
}

// round 16
// speedup vs baseline: 1.1219x; 1.0326x over previous
#include <cuda_runtime.h>
#include <cuda_fp16.h>
#include <math.h>

#define NN 50000
#define NP 50048
#define EE 400000
#define RR 4
#define MM (RR*NN)
#define SCAN_BLOCKS ((MM + 4095) / 4096)   // 49

#define FMA2(acc, w, a) asm("fma.rn.f32x2 %0, %1, %2, %0;" : "+l"(acc) : "l"(w), "l"(a))
#define PACK2(dst, lo, hi) asm("mov.b64 %0, {%1, %2};" : "=l"(dst) : "f"(lo), "f"(hi))
#define UNPACK2(lo, hi, src) asm("mov.b64 {%0, %1}, %2;" : "=f"(lo), "=f"(hi) : "l"(src))
#define CP_ASYNC16(saddr, gptr) \
    asm volatile("cp.async.cg.shared.global [%0], [%1], 16;" :: "r"(saddr), "l"(gptr))
#define CP_COMMIT() asm volatile("cp.async.commit_group;")
#define CP_WAIT0() asm volatile("cp.async.wait_group 0;" ::: "memory")

__device__ __forceinline__ unsigned smem_u32(const void* p) {
    return (unsigned)__cvta_generic_to_shared(p);
}

// ---------------- device scratch ----------------
__device__ __align__(16) float g_h2[NP * 64];
__device__ __align__(16) __half2 g_Hr[(size_t)RR * NP * 64];
__device__ __align__(16) float g_es[RR * NP * 2];
__device__ __align__(16) float g_ed[RR * NP * 2];
__device__ __align__(16) __half g_Fh[(size_t)NN * 512];   // fp16 GAT outputs (gather->mlp)
__device__ int g_deg[MM];           // zero at entry: zero-init first call, re-zeroed by k_scan3
__device__ int g_indptr[MM + 1];
__device__ int g_cursor[MM];
__device__ int g_nbr[2 * EE];
__device__ int g_blksum[64];
__device__ int g_blkoff[64];

// ---------------- CSR build ----------------
__global__ void k_hist(const int* __restrict__ ei, const float* __restrict__ ew) {
    int e = blockIdx.x * 256 + threadIdx.x;
    if (e >= EE) return;
    int s = ei[e];
    int d = ei[EE + e];
    float w = ew[e];
    if (w > 0.f) {
        atomicAdd(&g_deg[0 * NN + d], 1);
        atomicAdd(&g_deg[1 * NN + s], 1);
    } else if (w < 0.f) {
        atomicAdd(&g_deg[2 * NN + d], 1);
        atomicAdd(&g_deg[3 * NN + s], 1);
    }
}

__global__ void k_scan1() {
    __shared__ int sd[512];
    int t = threadIdx.x;
    int base = blockIdx.x * 4096 + t * 8;
    int v[8];
    int s = 0;
#pragma unroll
    for (int i = 0; i < 8; i++) {
        int idx = base + i;
        int x = (idx < MM) ? g_deg[idx] : 0;
        v[i] = s;
        s += x;
    }
    sd[t] = s;
    __syncthreads();
    int tot = s;
    for (int off = 1; off < 512; off <<= 1) {
        int y = (t >= off) ? sd[t - off] : 0;
        __syncthreads();
        sd[t] += y;
        __syncthreads();
    }
    int excl = sd[t] - tot;
#pragma unroll
    for (int i = 0; i < 8; i++) {
        int idx = base + i;
        if (idx < MM) g_indptr[idx] = excl + v[i];
    }
    if (t == 511) g_blksum[blockIdx.x] = sd[511];
}

__global__ void k_scan2(int nblk) {
    int lane = threadIdx.x;
    int v0 = (lane < nblk) ? g_blksum[lane] : 0;
    int v1 = (32 + lane < nblk) ? g_blksum[32 + lane] : 0;
    int s0 = v0;
#pragma unroll
    for (int off = 1; off < 32; off <<= 1) {
        int t = __shfl_up_sync(0xffffffffu, s0, off);
        if (lane >= off) s0 += t;
    }
    int tot0 = __shfl_sync(0xffffffffu, s0, 31);
    int s1 = v1;
#pragma unroll
    for (int off = 1; off < 32; off <<= 1) {
        int t = __shfl_up_sync(0xffffffffu, s1, off);
        if (lane >= off) s1 += t;
    }
    s1 += tot0;
    if (lane < nblk) g_blkoff[lane] = s0 - v0;
    if (32 + lane < nblk) g_blkoff[32 + lane] = s1 - v1;
    if (lane == 31) g_indptr[MM] = s1;
}

__global__ void k_scan3() {
    int off = g_blkoff[blockIdx.x];
    int idx = blockIdx.x * 4096 + threadIdx.x;
#pragma unroll
    for (int i = 0; i < 8; i++, idx += 512) {
        if (idx < MM) {
            int val = g_indptr[idx] + off;
            g_indptr[idx] = val;
            g_cursor[idx] = val;
            g_deg[idx] = 0;          // restore invariant for next call
        }
    }
}

__global__ void k_scatter(const int* __restrict__ ei, const float* __restrict__ ew) {
    int e = blockIdx.x * 256 + threadIdx.x;
    if (e >= EE) return;
    int s = ei[e];
    int d = ei[EE + e];
    float w = ew[e];
    if (w > 0.f) {
        int p0 = atomicAdd(&g_cursor[0 * NN + d], 1); g_nbr[p0] = s;
        int p1 = atomicAdd(&g_cursor[1 * NN + s], 1); g_nbr[p1] = d;
    } else if (w < 0.f) {
        int p2 = atomicAdd(&g_cursor[2 * NN + d], 1); g_nbr[p2] = s;
        int p3 = atomicAdd(&g_cursor[3 * NN + s], 1); g_nbr[p3] = d;
    }
}

// ---------------- per-relation feature GEMM + fused attention logits ----------------
// cp.async W fill; 4 cols x 16 nodes / thread; epilogue computes es/ed via packed
// butterfly reductions of the fp32 accumulators (replaces k_wa + k_logits).
__global__ __launch_bounds__(128) void k_feat(const float* __restrict__ xin,
                                              const float* __restrict__ W,
                                              const float* __restrict__ asrc,
                                              const float* __restrict__ adst,
                                              int l, int useX) {
    __shared__ __align__(16) float Ws[64 * 128];
    __shared__ __align__(16) float hsT[64 * 68];

    const float* hin = useX ? xin : g_h2;
    const int t = threadIdx.x;
    const int r = blockIdx.y;
    const int jc = t & 31;
    const int half = t >> 5;
    const float* Wp = W + (size_t)(l * RR + r) * 64 * 128;

    unsigned s_Ws = smem_u32(Ws);
#pragma unroll
    for (int i = 0; i < 16; i++) {
        int c4 = t + i * 128;
        CP_ASYNC16(s_Ws + c4 * 16, Wp + c4 * 4);
    }
    CP_COMMIT();

    int n0 = blockIdx.x * 64;
    for (int q = t; q < 64 * 64; q += 128) {
        int nn = q >> 6, k = q & 63;
        int n = n0 + nn;
        hsT[k * 68 + nn] = (n < NN) ? hin[(size_t)n * 64 + k] : 0.f;
    }
    CP_WAIT0();
    __syncthreads();

    unsigned long long acc[4][8];
#pragma unroll
    for (int c = 0; c < 4; c++)
#pragma unroll
        for (int p = 0; p < 8; p++) acc[c][p] = 0ull;

#pragma unroll 2
    for (int k = 0; k < 64; k++) {
        float w0 = Ws[k * 128 + jc];
        float w1 = Ws[k * 128 + jc + 32];
        float w2 = Ws[k * 128 + jc + 64];
        float w3 = Ws[k * 128 + jc + 96];
        unsigned long long wp0, wp1, wp2, wp3;
        PACK2(wp0, w0, w0); PACK2(wp1, w1, w1);
        PACK2(wp2, w2, w2); PACK2(wp3, w3, w3);
        const ulonglong2* hp = (const ulonglong2*)&hsT[k * 68 + half * 16];
#pragma unroll
        for (int q = 0; q < 4; q++) {
            ulonglong2 a = hp[q];
            FMA2(acc[0][2 * q], wp0, a.x); FMA2(acc[0][2 * q + 1], wp0, a.y);
            FMA2(acc[1][2 * q], wp1, a.x); FMA2(acc[1][2 * q + 1], wp1, a.y);
            FMA2(acc[2][2 * q], wp2, a.x); FMA2(acc[2][2 * q + 1], wp2, a.y);
            FMA2(acc[3][2 * q], wp3, a.x); FMA2(acc[3][2 * q + 1], wp3, a.y);
        }
    }

    // H store (fp16)
    __half2* Hrow = g_Hr + (size_t)r * NP * 64;
    int nb = n0 + half * 16;
#pragma unroll
    for (int p = 0; p < 8; p++) {
        float l0, h0, l1, h1, l2, h2, l3, h3;
        UNPACK2(l0, h0, acc[0][p]);
        UNPACK2(l1, h1, acc[1][p]);
        UNPACK2(l2, h2, acc[2][p]);
        UNPACK2(l3, h3, acc[3][p]);
        Hrow[(size_t)(nb + 2 * p) * 64 + jc]          = __floats2half2_rn(l0, l1);
        Hrow[(size_t)(nb + 2 * p + 1) * 64 + jc]      = __floats2half2_rn(h0, h1);
        Hrow[(size_t)(nb + 2 * p) * 64 + 32 + jc]     = __floats2half2_rn(l2, l3);
        Hrow[(size_t)(nb + 2 * p + 1) * 64 + 32 + jc] = __floats2half2_rn(h2, h3);
    }

    // fused logits: value v = p*4 + hd*2 + sd, lane v keeps the reduced pair.
    const float* ap = asrc + (size_t)(l * RR + r) * 128;
    const float* dp = adst + (size_t)(l * RR + r) * 128;
    unsigned long long as0, as1, as2, as3, ad0, ad1, ad2, ad3, ONE2;
    {
        float a_, b_;
        a_ = ap[jc];      PACK2(as0, a_, a_);
        a_ = ap[jc + 32]; PACK2(as1, a_, a_);
        a_ = ap[jc + 64]; PACK2(as2, a_, a_);
        a_ = ap[jc + 96]; PACK2(as3, a_, a_);
        a_ = dp[jc];      PACK2(ad0, a_, a_);
        a_ = dp[jc + 32]; PACK2(ad1, a_, a_);
        a_ = dp[jc + 64]; PACK2(ad2, a_, a_);
        a_ = dp[jc + 96]; PACK2(ad3, a_, a_);
        a_ = 1.0f; b_ = 1.0f; PACK2(ONE2, a_, b_);
    }
    unsigned long long keep = 0ull;
#pragma unroll
    for (int p = 0; p < 8; p++) {
#pragma unroll
        for (int combo = 0; combo < 4; combo++) {
            int hd = combo >> 1, sd = combo & 1;
            unsigned long long tsum = 0ull;
            unsigned long long m0 = sd ? (hd ? ad2 : ad0) : (hd ? as2 : as0);
            unsigned long long m1 = sd ? (hd ? ad3 : ad1) : (hd ? as3 : as1);
            FMA2(tsum, m0, acc[hd * 2 + 0][p]);
            FMA2(tsum, m1, acc[hd * 2 + 1][p]);
#pragma unroll
            for (int off = 16; off; off >>= 1) {
                unsigned long long o = __shfl_xor_sync(0xffffffffu, tsum, off);
                FMA2(tsum, ONE2, o);
            }
            if (jc == p * 4 + combo) keep = tsum;
        }
    }
    {
        int p = jc >> 2, hd = (jc >> 1) & 1, sd = jc & 1;
        float vlo, vhi;
        UNPACK2(vlo, vhi, keep);
        float* dst = (sd ? g_ed : g_es) + ((size_t)r * NP + nb + 2 * p) * 2 + hd;
        dst[0] = vlo;
        dst[2] = vhi;
    }
}

// ---------------- CSR gather: 2 rows per warp, 16 lanes/row, uint4 H loads ----------------
__global__ void k_gather(const float* __restrict__ gbias, int l) {
    int warp = (blockIdx.x * 256 + threadIdx.x) >> 5;
    int lane = threadIdx.x & 31;
    int hw = lane >> 4;
    int q = lane & 15;
    int gw = warp * 2 + hw;
    if (gw >= MM) return;
    int r = gw / NN;
    int d = gw - r * NN;
    int hd = q >> 3;
    int cbase = hd * 64 + 4 * (q & 7);

    const float* esr = g_es + (size_t)r * NP * 2;
    float edv = g_ed[((size_t)r * NP + d) * 2 + hd];
    const uint4* Hp = (const uint4*)(g_Hr + (size_t)r * NP * 64);

    float e0 = esr[d * 2 + hd] + edv;
    e0 = fmaxf(e0, 0.2f * e0);
    float p = __expf(e0);
    uint4 sv = Hp[(size_t)d * 16 + q];
    float2 f0 = __half22float2(*(__half2*)&sv.x);
    float2 f1 = __half22float2(*(__half2*)&sv.y);
    float2 f2 = __half22float2(*(__half2*)&sv.z);
    float2 f3 = __half22float2(*(__half2*)&sv.w);
    float a0 = p * f0.x, a4 = p * f0.y;
    float a1 = p * f1.x, a5 = p * f1.y;
    float a2 = p * f2.x, a6 = p * f2.y;
    float a3 = p * f3.x, a7 = p * f3.y;
    float den = p;
    float b0 = 0.f, b1 = 0.f, b2 = 0.f, b3 = 0.f;
    float b4 = 0.f, b5 = 0.f, b6 = 0.f, b7 = 0.f, denB = 0.f;

    int beg = g_indptr[gw];
    int end = g_indptr[gw + 1];
    int i = beg;
    for (; i + 2 <= end; i += 2) {
        int s0 = g_nbr[i];
        int s1 = g_nbr[i + 1];
        float ea = esr[s0 * 2 + hd] + edv;
        float eb = esr[s1 * 2 + hd] + edv;
        ea = fmaxf(ea, 0.2f * ea);
        eb = fmaxf(eb, 0.2f * eb);
        float pa = __expf(ea);
        float pb = __expf(eb);
        uint4 u0 = Hp[(size_t)s0 * 16 + q];
        uint4 u1 = Hp[(size_t)s1 * 16 + q];
        den += pa; denB += pb;
        float2 g0 = __half22float2(*(__half2*)&u0.x);
        float2 g1 = __half22float2(*(__half2*)&u0.y);
        float2 g2 = __half22float2(*(__half2*)&u0.z);
        float2 g3 = __half22float2(*(__half2*)&u0.w);
        a0 += pa * g0.x; a4 += pa * g0.y;
        a1 += pa * g1.x; a5 += pa * g1.y;
        a2 += pa * g2.x; a6 += pa * g2.y;
        a3 += pa * g3.x; a7 += pa * g3.y;
        float2 h0 = __half22float2(*(__half2*)&u1.x);
        float2 h1 = __half22float2(*(__half2*)&u1.y);
        float2 h2 = __half22float2(*(__half2*)&u1.z);
        float2 h3 = __half22float2(*(__half2*)&u1.w);
        b0 += pb * h0.x; b4 += pb * h0.y;
        b1 += pb * h1.x; b5 += pb * h1.y;
        b2 += pb * h2.x; b6 += pb * h2.y;
        b3 += pb * h3.x; b7 += pb * h3.y;
    }
    if (i < end) {
        int s0 = g_nbr[i];
        float ea = esr[s0 * 2 + hd] + edv;
        ea = fmaxf(ea, 0.2f * ea);
        float pa = __expf(ea);
        uint4 u0 = Hp[(size_t)s0 * 16 + q];
        den += pa;
        float2 g0 = __half22float2(*(__half2*)&u0.x);
        float2 g1 = __half22float2(*(__half2*)&u0.y);
        float2 g2 = __half22float2(*(__half2*)&u0.z);
        float2 g3 = __half22float2(*(__half2*)&u0.w);
        a0 += pa * g0.x; a4 += pa * g0.y;
        a1 += pa * g1.x; a5 += pa * g1.y;
        a2 += pa * g2.x; a6 += pa * g2.y;
        a3 += pa * g3.x; a7 += pa * g3.y;
    }
    den += denB;
    a0 += b0; a1 += b1; a2 += b2; a3 += b3;
    a4 += b4; a5 += b5; a6 += b6; a7 += b7;

    float inv = 1.f / den;
    const float* bp = gbias + (size_t)(l * RR + r) * 128 + cbase;
    __half2 o0 = __floats2half2_rn(a0 * inv + bp[0], a1 * inv + bp[1]);
    __half2 o1 = __floats2half2_rn(a2 * inv + bp[2], a3 * inv + bp[3]);
    __half2 o2 = __floats2half2_rn(a4 * inv + bp[32], a5 * inv + bp[33]);
    __half2 o3 = __floats2half2_rn(a6 * inv + bp[34], a7 * inv + bp[35]);
    __half* Fd = g_Fh + (size_t)d * 512 + r * 128 + cbase;
    *(uint2*)Fd = make_uint2(*(unsigned*)&o0, *(unsigned*)&o1);
    *(uint2*)(Fd + 32) = make_uint2(*(unsigned*)&o2, *(unsigned*)&o3);
}

// ---------------- MLP + residual + LayerNorm: cp.async double-buffered, fp16 F in ----------------
__global__ __launch_bounds__(128) void k_mlp(const float* __restrict__ xin,
                      const float* __restrict__ W1,
                      const float* __restrict__ b1,
                      const float* __restrict__ W2,
                      const float* __restrict__ b2,
                      const float* __restrict__ lng,
                      const float* __restrict__ lnb,
                      int l, float* __restrict__ outbuf, int isLast, int useX) {
    extern __shared__ __align__(16) float sm[];
    float* scomb = sm;                        // 16*576 = 9216 floats
    float* wbuf0 = scomb + 16 * 576;          // 4096
    float* wbuf1 = wbuf0 + 4096;              // 4096
    float* sRed = wbuf1 + 4096;               // 64

    const float* hin = useX ? xin : g_h2;
    float* hout = isLast ? outbuf : g_h2;

    int tid = threadIdx.x;
    int j = tid & 63;
    int g = tid >> 6;
    int lane = tid & 31;
    int w2 = (tid >> 5) & 1;
    int n0 = blockIdx.x * 16;

    const float* W1p = W1 + (size_t)l * 576 * 64;
    const float* W2p = W2 + (size_t)l * 4096;

    unsigned s_scomb = smem_u32(scomb);
    unsigned s_w0 = smem_u32(wbuf0);

#pragma unroll
    for (int i = 0; i < 2; i++) {
        int c4 = tid + i * 128;
        int nn = c4 >> 4, k4 = c4 & 15;
        CP_ASYNC16(s_scomb + (nn * 576 + k4 * 4) * 4,
                   hin + (size_t)(n0 + nn) * 64 + k4 * 4);
    }
#pragma unroll
    for (int i = 0; i < 8; i++) {
        int c4 = tid + i * 128;
        CP_ASYNC16(s_w0 + c4 * 16, W1p + c4 * 4);
    }
    CP_COMMIT();

#pragma unroll
    for (int i = 0; i < 16; i++) {
        int c = tid + i * 128;
        int nn = c >> 7, k4 = c & 127;
        uint2 raw = *(const uint2*)(g_Fh + (size_t)(n0 + nn) * 512 + k4 * 4);
        float2 f0 = __half22float2(*(__half2*)&raw.x);
        float2 f1 = __half22float2(*(__half2*)&raw.y);
        *(float4*)(scomb + nn * 576 + 64 + k4 * 4) = make_float4(f0.x, f0.y, f1.x, f1.y);
    }
    CP_WAIT0();
    __syncthreads();

    unsigned long long accA[8], accB[8];
#pragma unroll
    for (int n = 0; n < 8; n++) { accA[n] = 0ull; accB[n] = 0ull; }

    for (int kt = 0; kt < 9; kt++) {
        const float* nxt = (kt < 8) ? (W1p + (kt + 1) * 4096) : W2p;
        unsigned dstb = (kt & 1) ? s_w0 : smem_u32(wbuf1);
#pragma unroll
        for (int i = 0; i < 8; i++) {
            int c4 = tid + i * 128;
            CP_ASYNC16(dstb + c4 * 16, nxt + c4 * 4);
        }
        CP_COMMIT();

        const float* Wt = (kt & 1) ? wbuf1 : wbuf0;
#pragma unroll 4
        for (int kk4 = 0; kk4 < 16; kk4++) {
            float w0 = Wt[(kk4 * 4 + 0) * 64 + j];
            float w1 = Wt[(kk4 * 4 + 1) * 64 + j];
            float w2f = Wt[(kk4 * 4 + 2) * 64 + j];
            float w3 = Wt[(kk4 * 4 + 3) * 64 + j];
            unsigned long long wp01, wp23;
            PACK2(wp01, w0, w1);
            PACK2(wp23, w2f, w3);
#pragma unroll
            for (int n = 0; n < 8; n++) {
                ulonglong2 a = ((const ulonglong2*)(scomb + (g * 8 + n) * 576))[kt * 16 + kk4];
                FMA2(accA[n], wp01, a.x);
                FMA2(accB[n], wp23, a.y);
            }
        }
        CP_WAIT0();
        __syncthreads();
    }

    float bb = b1[l * 64 + j];
#pragma unroll
    for (int n = 0; n < 8; n++) {
        float lo, hi, lo2, hi2;
        UNPACK2(lo, hi, accA[n]);
        UNPACK2(lo2, hi2, accB[n]);
        scomb[(g * 8 + n) * 576 + 64 + j] = tanhf(bb + lo + hi + lo2 + hi2);
    }
    __syncthreads();

    const float* Wt2 = wbuf1;
    unsigned long long zA[8], zB[8];
#pragma unroll
    for (int n = 0; n < 8; n++) { zA[n] = 0ull; zB[n] = 0ull; }
#pragma unroll 4
    for (int kk4 = 0; kk4 < 16; kk4++) {
        float w0 = Wt2[(kk4 * 4 + 0) * 64 + j];
        float w1 = Wt2[(kk4 * 4 + 1) * 64 + j];
        float w2f = Wt2[(kk4 * 4 + 2) * 64 + j];
        float w3 = Wt2[(kk4 * 4 + 3) * 64 + j];
        unsigned long long wp01, wp23;
        PACK2(wp01, w0, w1);
        PACK2(wp23, w2f, w3);
#pragma unroll
        for (int n = 0; n < 8; n++) {
            ulonglong2 a = ((const ulonglong2*)(scomb + (g * 8 + n) * 576 + 64))[kk4];
            FMA2(zA[n], wp01, a.x);
            FMA2(zB[n], wp23, a.y);
        }
    }
    float z[8];
    float bb2 = b2[l * 64 + j];
#pragma unroll
    for (int n = 0; n < 8; n++) {
        float lo, hi, lo2, hi2;
        UNPACK2(lo, hi, zA[n]);
        UNPACK2(lo2, hi2, zB[n]);
        z[n] = bb2 + lo + hi + lo2 + hi2 + scomb[(g * 8 + n) * 576 + j];
    }

#pragma unroll
    for (int n = 0; n < 8; n++) {
        float a = z[n], bsq = z[n] * z[n];
#pragma unroll
        for (int o = 16; o; o >>= 1) {
            a += __shfl_down_sync(0xffffffffu, a, o);
            bsq += __shfl_down_sync(0xffffffffu, bsq, o);
        }
        if (lane == 0) {
            sRed[((g * 2 + w2) * 8 + n) * 2 + 0] = a;
            sRed[((g * 2 + w2) * 8 + n) * 2 + 1] = bsq;
        }
    }
    __syncthreads();

    float gj = lng[l * 64 + j];
    float bj = lnb[l * 64 + j];
#pragma unroll
    for (int n = 0; n < 8; n++) {
        float su = sRed[((g * 2 + 0) * 8 + n) * 2 + 0] + sRed[((g * 2 + 1) * 8 + n) * 2 + 0];
        float sq = sRed[((g * 2 + 0) * 8 + n) * 2 + 1] + sRed[((g * 2 + 1) * 8 + n) * 2 + 1];
        float mu = su * (1.f / 64.f);
        float var = sq * (1.f / 64.f) - mu * mu;
        float nrm = rsqrtf(var + 1e-5f);
        int n_ = n0 + g * 8 + n;
        hout[(size_t)n_ * 64 + j] = (z[n] - mu) * nrm * gj + bj;
    }
}

// ---------------- launch ----------------
extern "C" void kernel_launch(void* const* d_in, const int* in_sizes, int n_in,
                              void* d_out, int out_size) {
    const float* x   = (const float*)d_in[0];
    const int*   ei  = (const int*)d_in[1];
    const float* ew  = (const float*)d_in[2];
    const float* gW  = (const float*)d_in[3];
    const float* gas = (const float*)d_in[4];
    const float* gad = (const float*)d_in[5];
    const float* gb  = (const float*)d_in[6];
    const float* W1  = (const float*)d_in[7];
    const float* b1  = (const float*)d_in[8];
    const float* W2  = (const float*)d_in[9];
    const float* b2  = (const float*)d_in[10];
    const float* lg  = (const float*)d_in[11];
    const float* lb  = (const float*)d_in[12];
    float* out = (float*)d_out;

    const int mlp_smem = (16 * 576 + 4096 + 4096 + 64) * 4;   // 69888 B
    cudaFuncSetAttribute(k_mlp, cudaFuncAttributeMaxDynamicSharedMemorySize, mlp_smem);

    k_feat<<<dim3((NP + 63) / 64, RR), 128>>>(x, gW, gas, gad, 0, 1);
    k_hist<<<(EE + 255) / 256, 256>>>(ei, ew);
    k_scan1<<<SCAN_BLOCKS, 512>>>();
    k_scan2<<<1, 32>>>(SCAN_BLOCKS);
    k_scan3<<<SCAN_BLOCKS, 512>>>();
    k_scatter<<<(EE + 255) / 256, 256>>>(ei, ew);

    k_gather<<<MM / 16, 256>>>(gb, 0);
    k_mlp<<<NN / 16, 128, mlp_smem>>>(x, W1, b1, W2, b2, lg, lb, 0, out, 0, 1);

    // layer 1
    k_feat<<<dim3((NP + 63) / 64, RR), 128>>>(x, gW, gas, gad, 1, 0);
    k_gather<<<MM / 16, 256>>>(gb, 1);
    k_mlp<<<NN / 16, 128, mlp_smem>>>(x, W1, b1, W2, b2, lg, lb, 1, out, 1, 0);
}